// round 2
// baseline (speedup 1.0000x reference)
#include <cuda_runtime.h>
#include <cstdint>

// Problem constants (match reference_code)
#define N_ITEMS 100000
#define N_USERS 40000
#define EMB     100
#define ROW4    25          // EMB/4 float4 per row
#define NNZ_A   3200000
#define NNZ_U   1600000
#define BATCH   4096
#define LAYERS  3

// Scratch: __device__ globals (no allocations allowed)
__device__ float g_b0[(size_t)N_ITEMS * EMB];       // 40 MB ping
__device__ float g_b1[(size_t)N_ITEMS * EMB];       // 40 MB pong
__device__ float g_user[(size_t)N_USERS * EMB];     // 16 MB user_all accumulator

// ---------------------------------------------------------------------------
// init: b0 = embedding, total(d_out) = embedding, b1 = 0, user_all = 0
// ---------------------------------------------------------------------------
__global__ void k_init(const float4* __restrict__ emb, float4* __restrict__ total) {
    int i = blockIdx.x * blockDim.x + threadIdx.x;
    const int n_item4 = N_ITEMS * ROW4;     // 2.5M
    const int n_user4 = N_USERS * ROW4;     // 1.0M
    if (i < n_item4) {
        float4 v = emb[i];
        ((float4*)g_b0)[i] = v;
        total[i] = v;
        ((float4*)g_b1)[i] = make_float4(0.f, 0.f, 0.f, 0.f);
    }
    if (i < n_user4) {
        ((float4*)g_user)[i] = make_float4(0.f, 0.f, 0.f, 0.f);
    }
}

// ---------------------------------------------------------------------------
// COO SpMM scatter: one warp per nnz, lanes 0..24 each handle one float4.
// yout[row] += val * xin[col]   via red.global.add.v4.f32 (no-return atomics)
// ---------------------------------------------------------------------------
__global__ void k_spmm(const float* __restrict__ xin, float* __restrict__ yout,
                       const float* __restrict__ vals,
                       const int* __restrict__ rows,
                       const int* __restrict__ cols, int nnz) {
    int gtid = blockIdx.x * blockDim.x + threadIdx.x;
    int e    = gtid >> 5;           // warp index = nnz index
    int lane = threadIdx.x & 31;
    if (e >= nnz || lane >= ROW4) return;

    int   c = __ldg(&cols[e]);
    int   r = __ldg(&rows[e]);
    float v = __ldg(&vals[e]);

    const float4* src = (const float4*)(xin + (size_t)c * EMB);
    float4 xv = __ldg(&src[lane]);

    float4* dst = ((float4*)(yout + (size_t)r * EMB)) + lane;
    asm volatile("red.global.add.v4.f32 [%0], {%1, %2, %3, %4};"
                 :: "l"(dst),
                    "f"(xv.x * v), "f"(xv.y * v), "f"(xv.z * v), "f"(xv.w * v)
                 : "memory");
}

// ---------------------------------------------------------------------------
// consume: total += dst_layer; optionally zero the other buffer so it can be
// the next layer's atomic target. (ping-pong: no x-copy needed)
// ---------------------------------------------------------------------------
__global__ void k_consume(float4* __restrict__ total,
                          const float4* __restrict__ layer_out,
                          float4* __restrict__ zero_me, int do_zero) {
    int i = blockIdx.x * blockDim.x + threadIdx.x;
    if (i >= N_ITEMS * ROW4) return;
    float4 y = layer_out[i];
    float4 t = total[i];
    t.x += y.x; t.y += y.y; t.z += y.z; t.w += y.w;
    total[i] = t;
    if (do_zero)
        zero_me[i] = make_float4(0.f, 0.f, 0.f, 0.f);
}

// ---------------------------------------------------------------------------
// gather: out2[b] = user_all[user[b]]
// ---------------------------------------------------------------------------
__global__ void k_gather(const int* __restrict__ user, float4* __restrict__ out2) {
    int i = blockIdx.x * blockDim.x + threadIdx.x;
    if (i >= BATCH * ROW4) return;
    int b = i / ROW4;
    int j = i - b * ROW4;
    int u = __ldg(&user[b]);
    out2[i] = ((const float4*)g_user)[(size_t)u * ROW4 + j];
}

// ---------------------------------------------------------------------------
// Inputs (metadata order):
//  0 adj_vals f32[3.2M]   1 u_vals f32[1.6M]   2 embedding f32[100000,100]
//  3 user_embedding f32[40000,100]             4 adj_rows i32  5 adj_cols i32
//  6 u_rows i32  7 u_cols i32  8 user i32[4096]
// Output: concat(total [100000*100], user_all[user] [4096*100]) as f32
// ---------------------------------------------------------------------------
extern "C" void kernel_launch(void* const* d_in, const int* in_sizes, int n_in,
                              void* d_out, int out_size) {
    const float* adj_vals = (const float*)d_in[0];
    const float* u_vals   = (const float*)d_in[1];
    const float* emb      = (const float*)d_in[2];
    const int*   adj_rows = (const int*)d_in[4];
    const int*   adj_cols = (const int*)d_in[5];
    const int*   u_rows   = (const int*)d_in[6];
    const int*   u_cols   = (const int*)d_in[7];
    const int*   user     = (const int*)d_in[8];

    float* total = (float*)d_out;                       // [N_ITEMS*EMB]
    float* out2  = total + (size_t)N_ITEMS * EMB;       // [BATCH*EMB]

    float* b0 = nullptr; float* b1 = nullptr; float* ua = nullptr;
    cudaGetSymbolAddress((void**)&b0, g_b0);
    cudaGetSymbolAddress((void**)&b1, g_b1);
    cudaGetSymbolAddress((void**)&ua, g_user);

    const int TPB = 256;
    const int n_item4 = N_ITEMS * ROW4;
    const int item_blocks = (n_item4 + TPB - 1) / TPB;

    // init: b0 = emb, total = emb, b1 = 0, user_all = 0
    k_init<<<item_blocks, TPB>>>((const float4*)emb, (float4*)total);

    // 3 propagation layers with ping-pong buffers
    float* src = b0;
    float* dst = b1;
    for (int l = 0; l < LAYERS; l++) {
        long long threads = (long long)NNZ_A * 32;
        int blocks = (int)((threads + TPB - 1) / TPB);
        k_spmm<<<blocks, TPB>>>(src, dst, adj_vals, adj_rows, adj_cols, NNZ_A);
        // total += dst; zero src so it becomes next layer's atomic target
        int do_zero = (l < LAYERS - 1) ? 1 : 0;
        k_consume<<<item_blocks, TPB>>>((float4*)total, (const float4*)dst,
                                        (float4*)src, do_zero);
        float* t = src; src = dst; dst = t;
    }

    // user hypergraph projection: user_all = u_adj @ total
    {
        long long threads = (long long)NNZ_U * 32;
        int blocks = (int)((threads + TPB - 1) / TPB);
        k_spmm<<<blocks, TPB>>>(total, ua, u_vals, u_rows, u_cols, NNZ_U);
    }

    // gather batch rows
    {
        int n = BATCH * ROW4;
        k_gather<<<(n + TPB - 1) / TPB, TPB>>>(user, (float4*)out2);
    }
}

// round 3
// speedup vs baseline: 2.9138x; 2.9138x over previous
#include <cuda_runtime.h>
#include <cstdint>

// Problem constants (match reference_code)
#define N_ITEMS 100000
#define N_USERS 40000
#define EMB     100
#define ROW4    25          // EMB/4 float4 per row
#define NNZ_A   3200000
#define NNZ_U   1600000
#define BATCH   4096

#define SCAN_TPB 256
#define NB_A ((N_ITEMS + SCAN_TPB - 1) / SCAN_TPB)   // 391
#define NB_U ((N_USERS + SCAN_TPB - 1) / SCAN_TPB)   // 157

// ---------------------------------------------------------------------------
// Device scratch (no allocations allowed)
// ---------------------------------------------------------------------------
__device__ float g_b0[(size_t)N_ITEMS * EMB];   // 40 MB ping (layer outputs)
__device__ float g_b1[(size_t)N_ITEMS * EMB];   // 40 MB pong
__device__ int   g_cntA[N_ITEMS];               // histogram
__device__ int   g_ptrA[N_ITEMS];               // exclusive row offsets
__device__ int   g_runA[N_ITEMS];               // running counters for scatter
__device__ int2  g_cvA[NNZ_A];                  // row-sorted (col, val-bits)
__device__ int   g_cntU[N_USERS];
__device__ int   g_ptrU[N_USERS];
__device__ int   g_runU[N_USERS];
__device__ int2  g_cvU[NNZ_U];
__device__ int   g_bsum[1024];                  // scan block sums (reused)

// ---------------------------------------------------------------------------
// zero both histograms
// ---------------------------------------------------------------------------
__global__ void k_zero_cnt() {
    int i = blockIdx.x * blockDim.x + threadIdx.x;
    if (i < N_ITEMS) g_cntA[i] = 0;
    if (i < N_USERS) g_cntU[i] = 0;
}

// ---------------------------------------------------------------------------
// histogram of row indices
// ---------------------------------------------------------------------------
__global__ void k_hist(const int* __restrict__ rows, int* __restrict__ cnt, int nnz) {
    int e = blockIdx.x * blockDim.x + threadIdx.x;
    if (e < nnz) atomicAdd(&cnt[rows[e]], 1);
}

// ---------------------------------------------------------------------------
// 3-phase exclusive scan (n <= 256*1024)
// ---------------------------------------------------------------------------
__global__ void k_scan1(const int* __restrict__ cnt, int* __restrict__ ptr,
                        int* __restrict__ bsum, int n) {
    __shared__ int sh[SCAN_TPB];
    int tid = threadIdx.x;
    int i = blockIdx.x * SCAN_TPB + tid;
    int v = (i < n) ? cnt[i] : 0;
    sh[tid] = v;
    __syncthreads();
    for (int off = 1; off < SCAN_TPB; off <<= 1) {
        int t = (tid >= off) ? sh[tid - off] : 0;
        __syncthreads();
        sh[tid] += t;
        __syncthreads();
    }
    if (i < n) ptr[i] = sh[tid] - v;            // exclusive within block
    if (tid == SCAN_TPB - 1) bsum[blockIdx.x] = sh[tid];
}

__global__ void k_scan2(int* __restrict__ bsum, int nb) {   // 1 block, 1024 thr
    __shared__ int sh[1024];
    int tid = threadIdx.x;
    int v = (tid < nb) ? bsum[tid] : 0;
    sh[tid] = v;
    __syncthreads();
    for (int off = 1; off < 1024; off <<= 1) {
        int t = (tid >= off) ? sh[tid - off] : 0;
        __syncthreads();
        sh[tid] += t;
        __syncthreads();
    }
    if (tid < nb) bsum[tid] = sh[tid] - v;      // exclusive
}

__global__ void k_scan3(int* __restrict__ ptr, int* __restrict__ run,
                        const int* __restrict__ bsum, int n) {
    int i = blockIdx.x * SCAN_TPB + threadIdx.x;
    if (i < n) {
        int p = ptr[i] + bsum[blockIdx.x];
        ptr[i] = p;
        run[i] = p;
    }
}

// ---------------------------------------------------------------------------
// scatter edges into row-sorted packed (col, val) pairs
// ---------------------------------------------------------------------------
__global__ void k_scatter(const int* __restrict__ rows, const int* __restrict__ cols,
                          const float* __restrict__ vals, int* __restrict__ run,
                          int2* __restrict__ cv, int nnz) {
    int e = blockIdx.x * blockDim.x + threadIdx.x;
    if (e >= nnz) return;
    int pos = atomicAdd(&run[rows[e]], 1);
    cv[pos] = make_int2(cols[e], __float_as_int(vals[e]));
}

// ---------------------------------------------------------------------------
// CSR SpMM, warp per row, lanes 0..24 own one float4 of the row.
//   acc = sum_e val_e * x[col_e]
//   dst[row] = acc                      (if WRITE_DST)
//   total[row] = base[row] + acc        (base = emb if FIRST, else total)
// ---------------------------------------------------------------------------
template <bool FIRST, bool WRITE_DST>
__global__ void k_csr_spmm(const float4* __restrict__ x, float4* __restrict__ dst,
                           float4* __restrict__ total, const float4* __restrict__ emb,
                           const int* __restrict__ ptr, const int2* __restrict__ cv) {
    int w = (blockIdx.x * blockDim.x + threadIdx.x) >> 5;
    int lane = threadIdx.x & 31;
    if (w >= N_ITEMS) return;

    int e   = __ldg(&ptr[w]);
    int end = (w + 1 < N_ITEMS) ? __ldg(&ptr[w + 1]) : NNZ_A;
    bool active = lane < ROW4;

    float4 acc = make_float4(0.f, 0.f, 0.f, 0.f);
    for (; e + 1 < end; e += 2) {
        int2 p0 = __ldg(&cv[e]);
        int2 p1 = __ldg(&cv[e + 1]);
        if (active) {
            float v0 = __int_as_float(p0.y);
            float v1 = __int_as_float(p1.y);
            float4 a = __ldg(&x[p0.x * ROW4 + lane]);
            float4 b = __ldg(&x[p1.x * ROW4 + lane]);
            acc.x += v0 * a.x + v1 * b.x;
            acc.y += v0 * a.y + v1 * b.y;
            acc.z += v0 * a.z + v1 * b.z;
            acc.w += v0 * a.w + v1 * b.w;
        }
    }
    if (e < end) {
        int2 p0 = __ldg(&cv[e]);
        if (active) {
            float v0 = __int_as_float(p0.y);
            float4 a = __ldg(&x[p0.x * ROW4 + lane]);
            acc.x += v0 * a.x; acc.y += v0 * a.y;
            acc.z += v0 * a.z; acc.w += v0 * a.w;
        }
    }

    if (active) {
        int idx = w * ROW4 + lane;
        if (WRITE_DST) dst[idx] = acc;
        float4 t = FIRST ? __ldg(&emb[idx]) : total[idx];
        t.x += acc.x; t.y += acc.y; t.z += acc.z; t.w += acc.w;
        total[idx] = t;
    }
}

// ---------------------------------------------------------------------------
// user batch: out2[b] = sum_e u_val_e * total[u_col_e] over row user[b]
// warp per batch entry (computes only the 4096 needed user rows)
// ---------------------------------------------------------------------------
__global__ void k_user_batch(const float4* __restrict__ total,
                             const int* __restrict__ user,
                             const int* __restrict__ ptrU,
                             const int2* __restrict__ cvU,
                             float4* __restrict__ out2) {
    int w = (blockIdx.x * blockDim.x + threadIdx.x) >> 5;
    int lane = threadIdx.x & 31;
    if (w >= BATCH) return;

    int u   = __ldg(&user[w]);
    int e   = __ldg(&ptrU[u]);
    int end = (u + 1 < N_USERS) ? __ldg(&ptrU[u + 1]) : NNZ_U;
    bool active = lane < ROW4;

    float4 acc = make_float4(0.f, 0.f, 0.f, 0.f);
    for (; e + 1 < end; e += 2) {
        int2 p0 = __ldg(&cvU[e]);
        int2 p1 = __ldg(&cvU[e + 1]);
        if (active) {
            float v0 = __int_as_float(p0.y);
            float v1 = __int_as_float(p1.y);
            float4 a = __ldg(&total[p0.x * ROW4 + lane]);
            float4 b = __ldg(&total[p1.x * ROW4 + lane]);
            acc.x += v0 * a.x + v1 * b.x;
            acc.y += v0 * a.y + v1 * b.y;
            acc.z += v0 * a.z + v1 * b.z;
            acc.w += v0 * a.w + v1 * b.w;
        }
    }
    if (e < end) {
        int2 p0 = __ldg(&cvU[e]);
        if (active) {
            float v0 = __int_as_float(p0.y);
            float4 a = __ldg(&total[p0.x * ROW4 + lane]);
            acc.x += v0 * a.x; acc.y += v0 * a.y;
            acc.z += v0 * a.z; acc.w += v0 * a.w;
        }
    }
    if (active) out2[w * ROW4 + lane] = acc;
}

// ---------------------------------------------------------------------------
// Inputs (metadata order):
//  0 adj_vals f32[3.2M]   1 u_vals f32[1.6M]   2 embedding f32[100000,100]
//  3 user_embedding f32[40000,100]             4 adj_rows i32  5 adj_cols i32
//  6 u_rows i32  7 u_cols i32  8 user i32[4096]
// Output: concat(total [100000*100], user_all[user] [4096*100]) as f32
// ---------------------------------------------------------------------------
extern "C" void kernel_launch(void* const* d_in, const int* in_sizes, int n_in,
                              void* d_out, int out_size) {
    const float* adj_vals = (const float*)d_in[0];
    const float* u_vals   = (const float*)d_in[1];
    const float* emb      = (const float*)d_in[2];
    const int*   adj_rows = (const int*)d_in[4];
    const int*   adj_cols = (const int*)d_in[5];
    const int*   u_rows   = (const int*)d_in[6];
    const int*   u_cols   = (const int*)d_in[7];
    const int*   user     = (const int*)d_in[8];

    float* total = (float*)d_out;                    // [N_ITEMS*EMB]
    float* out2  = total + (size_t)N_ITEMS * EMB;    // [BATCH*EMB]

    float *b0, *b1;
    int *cntA, *ptrA, *runA, *cntU, *ptrU, *runU, *bsum;
    int2 *cvA, *cvU;
    cudaGetSymbolAddress((void**)&b0,   g_b0);
    cudaGetSymbolAddress((void**)&b1,   g_b1);
    cudaGetSymbolAddress((void**)&cntA, g_cntA);
    cudaGetSymbolAddress((void**)&ptrA, g_ptrA);
    cudaGetSymbolAddress((void**)&runA, g_runA);
    cudaGetSymbolAddress((void**)&cvA,  g_cvA);
    cudaGetSymbolAddress((void**)&cntU, g_cntU);
    cudaGetSymbolAddress((void**)&ptrU, g_ptrU);
    cudaGetSymbolAddress((void**)&runU, g_runU);
    cudaGetSymbolAddress((void**)&cvU,  g_cvU);
    cudaGetSymbolAddress((void**)&bsum, g_bsum);

    const int TPB = 256;

    // ---- build CSR for both graphs ----
    k_zero_cnt<<<(N_ITEMS + TPB - 1) / TPB, TPB>>>();
    k_hist<<<(NNZ_A + TPB - 1) / TPB, TPB>>>(adj_rows, cntA, NNZ_A);
    k_hist<<<(NNZ_U + TPB - 1) / TPB, TPB>>>(u_rows, cntU, NNZ_U);

    k_scan1<<<NB_A, SCAN_TPB>>>(cntA, ptrA, bsum, N_ITEMS);
    k_scan2<<<1, 1024>>>(bsum, NB_A);
    k_scan3<<<NB_A, SCAN_TPB>>>(ptrA, runA, bsum, N_ITEMS);

    k_scatter<<<(NNZ_A + TPB - 1) / TPB, TPB>>>(adj_rows, adj_cols, adj_vals,
                                                runA, cvA, NNZ_A);

    k_scan1<<<NB_U, SCAN_TPB>>>(cntU, ptrU, bsum, N_USERS);
    k_scan2<<<1, 1024>>>(bsum, NB_U);
    k_scan3<<<NB_U, SCAN_TPB>>>(ptrU, runU, bsum, N_USERS);

    k_scatter<<<(NNZ_U + TPB - 1) / TPB, TPB>>>(u_rows, u_cols, u_vals,
                                                runU, cvU, NNZ_U);

    // ---- 3 propagation layers (warp per row, atomic-free) ----
    const int spmm_blocks = (N_ITEMS * 32 + TPB - 1) / TPB;
    // layer 1: x=emb -> b0;  total = emb + acc
    k_csr_spmm<true,  true ><<<spmm_blocks, TPB>>>((const float4*)emb, (float4*)b0,
        (float4*)total, (const float4*)emb, ptrA, cvA);
    // layer 2: x=b0 -> b1;   total += acc
    k_csr_spmm<false, true ><<<spmm_blocks, TPB>>>((const float4*)b0, (float4*)b1,
        (float4*)total, (const float4*)emb, ptrA, cvA);
    // layer 3: x=b1 (no dst); total += acc
    k_csr_spmm<false, false><<<spmm_blocks, TPB>>>((const float4*)b1, (float4*)b0,
        (float4*)total, (const float4*)emb, ptrA, cvA);

    // ---- user projection, batch rows only ----
    const int ub_blocks = (BATCH * 32 + TPB - 1) / TPB;
    k_user_batch<<<ub_blocks, TPB>>>((const float4*)total, user, ptrU, cvU,
                                     (float4*)out2);
}

// round 4
// speedup vs baseline: 3.3332x; 1.1439x over previous
#include <cuda_runtime.h>
#include <cuda_fp16.h>
#include <cstdint>

// Problem constants (match reference_code)
#define N_ITEMS 100000
#define N_USERS 40000
#define EMB     100
#define ROW4    25          // EMB/4 float4 (or uint2-of-4-halves) per row
#define NNZ_A   3200000
#define NNZ_U   1600000
#define BATCH   4096

#define SCAN_TPB 256
#define NB_A ((N_ITEMS + SCAN_TPB - 1) / SCAN_TPB)   // 391
#define NB_U ((N_USERS + SCAN_TPB - 1) / SCAN_TPB)   // 157

// ---------------------------------------------------------------------------
// Device scratch (no allocations allowed)
// ---------------------------------------------------------------------------
__device__ uint2 g_eh[(size_t)N_ITEMS * ROW4];  // 20 MB: fp16 embedding
__device__ uint2 g_h0[(size_t)N_ITEMS * ROW4];  // 20 MB: fp16 x1
__device__ uint2 g_h1[(size_t)N_ITEMS * ROW4];  // 20 MB: fp16 x2
__device__ int   g_cntA[N_ITEMS];
__device__ int   g_ptrA[N_ITEMS];
__device__ int   g_runA[N_ITEMS];
__device__ int2  g_cvA[NNZ_A];                  // row-sorted (col, val-bits)
__device__ int   g_cntU[N_USERS];
__device__ int   g_ptrU[N_USERS];
__device__ int   g_runU[N_USERS];
__device__ int2  g_cvU[NNZ_U];
__device__ int   g_bsum[1024];

// ---------------------------------------------------------------------------
// zero histograms + convert embedding fp32 -> fp16 (fused)
// ---------------------------------------------------------------------------
__global__ void k_prep(const float4* __restrict__ emb) {
    int i = blockIdx.x * blockDim.x + threadIdx.x;
    if (i < N_ITEMS) g_cntA[i] = 0;
    if (i < N_USERS) g_cntU[i] = 0;
    if (i < N_ITEMS * ROW4) {
        float4 v = emb[i];
        __half2 lo = __floats2half2_rn(v.x, v.y);
        __half2 hi = __floats2half2_rn(v.z, v.w);
        uint2 h;
        h.x = *reinterpret_cast<uint32_t*>(&lo);
        h.y = *reinterpret_cast<uint32_t*>(&hi);
        g_eh[i] = h;
    }
}

// ---------------------------------------------------------------------------
// merged histogram of row indices (A then U)
// ---------------------------------------------------------------------------
__global__ void k_hist2(const int* __restrict__ rowsA, const int* __restrict__ rowsU) {
    int e = blockIdx.x * blockDim.x + threadIdx.x;
    if (e < NNZ_A)                atomicAdd(&g_cntA[rowsA[e]], 1);
    else if (e < NNZ_A + NNZ_U)   atomicAdd(&g_cntU[rowsU[e - NNZ_A]], 1);
}

// ---------------------------------------------------------------------------
// 3-phase exclusive scan
// ---------------------------------------------------------------------------
__global__ void k_scan1(const int* __restrict__ cnt, int* __restrict__ ptr,
                        int* __restrict__ bsum, int n) {
    __shared__ int sh[SCAN_TPB];
    int tid = threadIdx.x;
    int i = blockIdx.x * SCAN_TPB + tid;
    int v = (i < n) ? cnt[i] : 0;
    sh[tid] = v;
    __syncthreads();
    for (int off = 1; off < SCAN_TPB; off <<= 1) {
        int t = (tid >= off) ? sh[tid - off] : 0;
        __syncthreads();
        sh[tid] += t;
        __syncthreads();
    }
    if (i < n) ptr[i] = sh[tid] - v;
    if (tid == SCAN_TPB - 1) bsum[blockIdx.x] = sh[tid];
}

__global__ void k_scan2(int* __restrict__ bsum, int nb) {   // 1 block, 1024 thr
    __shared__ int sh[1024];
    int tid = threadIdx.x;
    int v = (tid < nb) ? bsum[tid] : 0;
    sh[tid] = v;
    __syncthreads();
    for (int off = 1; off < 1024; off <<= 1) {
        int t = (tid >= off) ? sh[tid - off] : 0;
        __syncthreads();
        sh[tid] += t;
        __syncthreads();
    }
    if (tid < nb) bsum[tid] = sh[tid] - v;
}

__global__ void k_scan3(int* __restrict__ ptr, int* __restrict__ run,
                        const int* __restrict__ bsum, int n) {
    int i = blockIdx.x * SCAN_TPB + threadIdx.x;
    if (i < n) {
        int p = ptr[i] + bsum[blockIdx.x];
        ptr[i] = p;
        run[i] = p;
    }
}

// ---------------------------------------------------------------------------
// merged scatter into row-sorted packed (col, val) pairs
// ---------------------------------------------------------------------------
__global__ void k_scatter2(const int* __restrict__ rowsA, const int* __restrict__ colsA,
                           const float* __restrict__ valsA,
                           const int* __restrict__ rowsU, const int* __restrict__ colsU,
                           const float* __restrict__ valsU) {
    int e = blockIdx.x * blockDim.x + threadIdx.x;
    if (e < NNZ_A) {
        int pos = atomicAdd(&g_runA[rowsA[e]], 1);
        g_cvA[pos] = make_int2(colsA[e], __float_as_int(valsA[e]));
    } else if (e < NNZ_A + NNZ_U) {
        int eu = e - NNZ_A;
        int pos = atomicAdd(&g_runU[rowsU[eu]], 1);
        g_cvU[pos] = make_int2(colsU[eu], __float_as_int(valsU[eu]));
    }
}

// ---------------------------------------------------------------------------
// fp16 gather helper: 4 halves -> fma into 4-float acc
// ---------------------------------------------------------------------------
__device__ __forceinline__ void fma_h4(float4& acc, uint2 h, float v) {
    __half2 lo = *reinterpret_cast<__half2*>(&h.x);
    __half2 hi = *reinterpret_cast<__half2*>(&h.y);
    float2 a = __half22float2(lo);
    float2 b = __half22float2(hi);
    acc.x += v * a.x; acc.y += v * a.y;
    acc.z += v * b.x; acc.w += v * b.y;
}

__device__ __forceinline__ float4 h4_to_f4(uint2 h) {
    __half2 lo = *reinterpret_cast<__half2*>(&h.x);
    __half2 hi = *reinterpret_cast<__half2*>(&h.y);
    float2 a = __half22float2(lo);
    float2 b = __half22float2(hi);
    return make_float4(a.x, a.y, b.x, b.y);
}

// ---------------------------------------------------------------------------
// CSR SpMM layers 1,2: warp per row, lanes 0..24 own 4 dims (one uint2).
//   dst_h[row] = fp16( sum_e val_e * fp32(x_h[col_e]) )
// ---------------------------------------------------------------------------
__global__ void k_spmm_h(const uint2* __restrict__ xh, uint2* __restrict__ dsth,
                         const int* __restrict__ ptr, const int2* __restrict__ cv) {
    int w = (blockIdx.x * blockDim.x + threadIdx.x) >> 5;
    int lane = threadIdx.x & 31;
    if (w >= N_ITEMS) return;

    int e   = __ldg(&ptr[w]);
    int end = (w + 1 < N_ITEMS) ? __ldg(&ptr[w + 1]) : NNZ_A;
    bool active = lane < ROW4;

    float4 acc = make_float4(0.f, 0.f, 0.f, 0.f);
    for (; e + 1 < end; e += 2) {
        int2 p0 = __ldg(&cv[e]);
        int2 p1 = __ldg(&cv[e + 1]);
        if (active) {
            uint2 a = __ldg(&xh[p0.x * ROW4 + lane]);
            uint2 b = __ldg(&xh[p1.x * ROW4 + lane]);
            fma_h4(acc, a, __int_as_float(p0.y));
            fma_h4(acc, b, __int_as_float(p1.y));
        }
    }
    if (e < end) {
        int2 p0 = __ldg(&cv[e]);
        if (active) {
            uint2 a = __ldg(&xh[p0.x * ROW4 + lane]);
            fma_h4(acc, a, __int_as_float(p0.y));
        }
    }

    if (active) {
        __half2 lo = __floats2half2_rn(acc.x, acc.y);
        __half2 hi = __floats2half2_rn(acc.z, acc.w);
        uint2 h;
        h.x = *reinterpret_cast<uint32_t*>(&lo);
        h.y = *reinterpret_cast<uint32_t*>(&hi);
        dsth[w * ROW4 + lane] = h;
    }
}

// ---------------------------------------------------------------------------
// Layer 3 (final): acc = A @ x2 ; total = emb + x1 + x2 + acc  (fp32 out)
// ---------------------------------------------------------------------------
__global__ void k_spmm_final(const uint2* __restrict__ x2h,
                             const uint2* __restrict__ x1h,
                             const float4* __restrict__ emb,
                             float4* __restrict__ total,
                             const int* __restrict__ ptr, const int2* __restrict__ cv) {
    int w = (blockIdx.x * blockDim.x + threadIdx.x) >> 5;
    int lane = threadIdx.x & 31;
    if (w >= N_ITEMS) return;

    int e   = __ldg(&ptr[w]);
    int end = (w + 1 < N_ITEMS) ? __ldg(&ptr[w + 1]) : NNZ_A;
    bool active = lane < ROW4;

    float4 acc = make_float4(0.f, 0.f, 0.f, 0.f);
    for (; e + 1 < end; e += 2) {
        int2 p0 = __ldg(&cv[e]);
        int2 p1 = __ldg(&cv[e + 1]);
        if (active) {
            uint2 a = __ldg(&x2h[p0.x * ROW4 + lane]);
            uint2 b = __ldg(&x2h[p1.x * ROW4 + lane]);
            fma_h4(acc, a, __int_as_float(p0.y));
            fma_h4(acc, b, __int_as_float(p1.y));
        }
    }
    if (e < end) {
        int2 p0 = __ldg(&cv[e]);
        if (active) {
            uint2 a = __ldg(&x2h[p0.x * ROW4 + lane]);
            fma_h4(acc, a, __int_as_float(p0.y));
        }
    }

    if (active) {
        int idx = w * ROW4 + lane;
        float4 t  = __ldg(&emb[idx]);
        float4 x1 = h4_to_f4(__ldg(&x1h[idx]));
        float4 x2 = h4_to_f4(__ldg(&x2h[idx]));
        t.x += x1.x + x2.x + acc.x;
        t.y += x1.y + x2.y + acc.y;
        t.z += x1.z + x2.z + acc.z;
        t.w += x1.w + x2.w + acc.w;
        total[idx] = t;
    }
}

// ---------------------------------------------------------------------------
// user batch: out2[b] = sum_e u_val_e * total[u_col_e] over row user[b]
// (fp32 gather of total — only 4096 rows, traffic is small)
// ---------------------------------------------------------------------------
__global__ void k_user_batch(const float4* __restrict__ total,
                             const int* __restrict__ user,
                             const int* __restrict__ ptrU,
                             const int2* __restrict__ cvU,
                             float4* __restrict__ out2) {
    int w = (blockIdx.x * blockDim.x + threadIdx.x) >> 5;
    int lane = threadIdx.x & 31;
    if (w >= BATCH) return;

    int u   = __ldg(&user[w]);
    int e   = __ldg(&ptrU[u]);
    int end = (u + 1 < N_USERS) ? __ldg(&ptrU[u + 1]) : NNZ_U;
    bool active = lane < ROW4;

    float4 acc = make_float4(0.f, 0.f, 0.f, 0.f);
    for (; e + 1 < end; e += 2) {
        int2 p0 = __ldg(&cvU[e]);
        int2 p1 = __ldg(&cvU[e + 1]);
        if (active) {
            float v0 = __int_as_float(p0.y);
            float v1 = __int_as_float(p1.y);
            float4 a = __ldg(&total[p0.x * ROW4 + lane]);
            float4 b = __ldg(&total[p1.x * ROW4 + lane]);
            acc.x += v0 * a.x + v1 * b.x;
            acc.y += v0 * a.y + v1 * b.y;
            acc.z += v0 * a.z + v1 * b.z;
            acc.w += v0 * a.w + v1 * b.w;
        }
    }
    if (e < end) {
        int2 p0 = __ldg(&cvU[e]);
        if (active) {
            float v0 = __int_as_float(p0.y);
            float4 a = __ldg(&total[p0.x * ROW4 + lane]);
            acc.x += v0 * a.x; acc.y += v0 * a.y;
            acc.z += v0 * a.z; acc.w += v0 * a.w;
        }
    }
    if (active) out2[w * ROW4 + lane] = acc;
}

// ---------------------------------------------------------------------------
// Inputs (metadata order):
//  0 adj_vals f32[3.2M]   1 u_vals f32[1.6M]   2 embedding f32[100000,100]
//  3 user_embedding f32[40000,100]             4 adj_rows i32  5 adj_cols i32
//  6 u_rows i32  7 u_cols i32  8 user i32[4096]
// Output: concat(total [100000*100], user_all[user] [4096*100]) as f32
// ---------------------------------------------------------------------------
extern "C" void kernel_launch(void* const* d_in, const int* in_sizes, int n_in,
                              void* d_out, int out_size) {
    const float* adj_vals = (const float*)d_in[0];
    const float* u_vals   = (const float*)d_in[1];
    const float* emb      = (const float*)d_in[2];
    const int*   adj_rows = (const int*)d_in[4];
    const int*   adj_cols = (const int*)d_in[5];
    const int*   u_rows   = (const int*)d_in[6];
    const int*   u_cols   = (const int*)d_in[7];
    const int*   user     = (const int*)d_in[8];

    float* total = (float*)d_out;                    // [N_ITEMS*EMB]
    float* out2  = total + (size_t)N_ITEMS * EMB;    // [BATCH*EMB]

    uint2 *eh, *h0, *h1;
    int *cntA, *ptrA, *cntU, *ptrU, *bsum, *runA, *runU;
    cudaGetSymbolAddress((void**)&eh,   g_eh);
    cudaGetSymbolAddress((void**)&h0,   g_h0);
    cudaGetSymbolAddress((void**)&h1,   g_h1);
    cudaGetSymbolAddress((void**)&cntA, g_cntA);
    cudaGetSymbolAddress((void**)&ptrA, g_ptrA);
    cudaGetSymbolAddress((void**)&runA, g_runA);
    cudaGetSymbolAddress((void**)&cntU, g_cntU);
    cudaGetSymbolAddress((void**)&ptrU, g_ptrU);
    cudaGetSymbolAddress((void**)&runU, g_runU);
    cudaGetSymbolAddress((void**)&bsum, g_bsum);
    int2 *cvA, *cvU;
    cudaGetSymbolAddress((void**)&cvA,  g_cvA);
    cudaGetSymbolAddress((void**)&cvU,  g_cvU);
    (void)runA; (void)runU; (void)cvA; (void)cvU;

    const int TPB = 256;

    // ---- prep: zero histograms + fp16 embedding copy ----
    k_prep<<<(N_ITEMS * ROW4 + TPB - 1) / TPB, TPB>>>((const float4*)emb);

    // ---- build CSR for both graphs (merged hist / merged scatter) ----
    k_hist2<<<(NNZ_A + NNZ_U + TPB - 1) / TPB, TPB>>>(adj_rows, u_rows);

    k_scan1<<<NB_A, SCAN_TPB>>>(cntA, ptrA, bsum, N_ITEMS);
    k_scan2<<<1, 1024>>>(bsum, NB_A);
    k_scan3<<<NB_A, SCAN_TPB>>>(ptrA, runA, bsum, N_ITEMS);

    k_scan1<<<NB_U, SCAN_TPB>>>(cntU, ptrU, bsum, N_USERS);
    k_scan2<<<1, 1024>>>(bsum, NB_U);
    k_scan3<<<NB_U, SCAN_TPB>>>(ptrU, runU, bsum, N_USERS);

    k_scatter2<<<(NNZ_A + NNZ_U + TPB - 1) / TPB, TPB>>>(
        adj_rows, adj_cols, adj_vals, u_rows, u_cols, u_vals);

    // ---- 3 propagation layers (warp per row, fp16 gathers, fp32 accum) ----
    const int spmm_blocks = (N_ITEMS * 32 + TPB - 1) / TPB;
    k_spmm_h<<<spmm_blocks, TPB>>>(eh, h0, ptrA, cvA);                 // x1
    k_spmm_h<<<spmm_blocks, TPB>>>(h0, h1, ptrA, cvA);                 // x2
    k_spmm_final<<<spmm_blocks, TPB>>>(h1, h0, (const float4*)emb,
                                       (float4*)total, ptrA, cvA);     // total

    // ---- user projection, batch rows only ----
    const int ub_blocks = (BATCH * 32 + TPB - 1) / TPB;
    k_user_batch<<<ub_blocks, TPB>>>((const float4*)total, user, ptrU, cvU,
                                     (float4*)out2);
}

// round 5
// speedup vs baseline: 3.7407x; 1.1222x over previous
#include <cuda_runtime.h>
#include <cuda_fp16.h>
#include <cstdint>

// Problem constants (match reference_code)
#define N_ITEMS 100000
#define N_USERS 40000
#define N_TOTAL (N_ITEMS + N_USERS)     // 140000 combined row space
#define EMB     100
#define ROW4    25
#define NNZ_A   3200000
#define NNZ_U   1600000
#define NNZ_T   (NNZ_A + NNZ_U)         // 4.8M combined edges
#define BATCH   4096

#define SCAN_TPB 256
#define NB_T ((N_TOTAL + SCAN_TPB - 1) / SCAN_TPB)   // 547 (<1024)

// ---------------------------------------------------------------------------
// Device scratch (no allocations allowed)
// ---------------------------------------------------------------------------
__device__ uint2 g_eh[(size_t)N_ITEMS * ROW4];  // 20 MB fp16 embedding
__device__ uint2 g_h0[(size_t)N_ITEMS * ROW4];  // 20 MB fp16 x1
__device__ uint2 g_h1[(size_t)N_ITEMS * ROW4];  // 20 MB fp16 x2
__device__ int   g_cnt[N_TOTAL];                // combined histogram
__device__ int   g_ptr[N_TOTAL];                // combined exclusive offsets
__device__ int   g_run[N_TOTAL];                // scatter cursors
__device__ int2  g_cv[NNZ_T];                   // row-sorted (col, val-bits)
__device__ int   g_bsum[1024];

// ---------------------------------------------------------------------------
// prep: zero combined histogram + fp16 embedding conversion (fused)
// ---------------------------------------------------------------------------
__global__ void k_prep(const float4* __restrict__ emb) {
    int i = blockIdx.x * blockDim.x + threadIdx.x;
    if (i < N_TOTAL) g_cnt[i] = 0;
    if (i < N_ITEMS * ROW4) {
        float4 v = emb[i];
        __half2 lo = __floats2half2_rn(v.x, v.y);
        __half2 hi = __floats2half2_rn(v.z, v.w);
        uint2 h;
        h.x = *reinterpret_cast<uint32_t*>(&lo);
        h.y = *reinterpret_cast<uint32_t*>(&hi);
        g_eh[i] = h;
    }
}

// ---------------------------------------------------------------------------
// combined histogram (A rows at [0,N_ITEMS), U rows at [N_ITEMS,N_TOTAL))
// ---------------------------------------------------------------------------
__global__ void k_hist(const int* __restrict__ rowsA, const int* __restrict__ rowsU) {
    int e = blockIdx.x * blockDim.x + threadIdx.x;
    if (e < NNZ_A)            atomicAdd(&g_cnt[rowsA[e]], 1);
    else if (e < NNZ_T)       atomicAdd(&g_cnt[N_ITEMS + rowsU[e - NNZ_A]], 1);
}

// ---------------------------------------------------------------------------
// 3-phase exclusive scan over combined histogram
// ---------------------------------------------------------------------------
__global__ void k_scan1(const int* __restrict__ cnt, int* __restrict__ ptr,
                        int* __restrict__ bsum, int n) {
    __shared__ int sh[SCAN_TPB];
    int tid = threadIdx.x;
    int i = blockIdx.x * SCAN_TPB + tid;
    int v = (i < n) ? cnt[i] : 0;
    sh[tid] = v;
    __syncthreads();
    for (int off = 1; off < SCAN_TPB; off <<= 1) {
        int t = (tid >= off) ? sh[tid - off] : 0;
        __syncthreads();
        sh[tid] += t;
        __syncthreads();
    }
    if (i < n) ptr[i] = sh[tid] - v;
    if (tid == SCAN_TPB - 1) bsum[blockIdx.x] = sh[tid];
}

__global__ void k_scan2(int* __restrict__ bsum, int nb) {   // 1 block, 1024 thr
    __shared__ int sh[1024];
    int tid = threadIdx.x;
    int v = (tid < nb) ? bsum[tid] : 0;
    sh[tid] = v;
    __syncthreads();
    for (int off = 1; off < 1024; off <<= 1) {
        int t = (tid >= off) ? sh[tid - off] : 0;
        __syncthreads();
        sh[tid] += t;
        __syncthreads();
    }
    if (tid < nb) bsum[tid] = sh[tid] - v;
}

__global__ void k_scan3(int* __restrict__ ptr, int* __restrict__ run,
                        const int* __restrict__ bsum, int n) {
    int i = blockIdx.x * SCAN_TPB + threadIdx.x;
    if (i < n) {
        int p = ptr[i] + bsum[blockIdx.x];
        ptr[i] = p;
        run[i] = p;
    }
}

// ---------------------------------------------------------------------------
// combined scatter into row-sorted packed (col, val) pairs
// ---------------------------------------------------------------------------
__global__ void k_scatter(const int* __restrict__ rowsA, const int* __restrict__ colsA,
                          const float* __restrict__ valsA,
                          const int* __restrict__ rowsU, const int* __restrict__ colsU,
                          const float* __restrict__ valsU) {
    int e = blockIdx.x * blockDim.x + threadIdx.x;
    if (e < NNZ_A) {
        int pos = atomicAdd(&g_run[rowsA[e]], 1);
        g_cv[pos] = make_int2(colsA[e], __float_as_int(valsA[e]));
    } else if (e < NNZ_T) {
        int eu = e - NNZ_A;
        int pos = atomicAdd(&g_run[N_ITEMS + rowsU[eu]], 1);
        g_cv[pos] = make_int2(colsU[eu], __float_as_int(valsU[eu]));
    }
}

// ---------------------------------------------------------------------------
// fp16 helpers
// ---------------------------------------------------------------------------
__device__ __forceinline__ void fma_h4(float4& acc, uint2 h, float v) {
    __half2 lo = *reinterpret_cast<__half2*>(&h.x);
    __half2 hi = *reinterpret_cast<__half2*>(&h.y);
    float2 a = __half22float2(lo);
    float2 b = __half22float2(hi);
    acc.x += v * a.x; acc.y += v * a.y;
    acc.z += v * b.x; acc.w += v * b.y;
}

__device__ __forceinline__ float4 h4_to_f4(uint2 h) {
    __half2 lo = *reinterpret_cast<__half2*>(&h.x);
    __half2 hi = *reinterpret_cast<__half2*>(&h.y);
    float2 a = __half22float2(lo);
    float2 b = __half22float2(hi);
    return make_float4(a.x, a.y, b.x, b.y);
}

// ---------------------------------------------------------------------------
// shared CSR gather loop body (unroll-4, front-batched loads)
// ---------------------------------------------------------------------------
__device__ __forceinline__ float4 csr_row_gather(const uint2* __restrict__ xh,
                                                 int e, int end, int lane,
                                                 bool active) {
    float4 acc = make_float4(0.f, 0.f, 0.f, 0.f);
    for (; e + 3 < end; e += 4) {
        int2 p0 = __ldg(&g_cv[e]);
        int2 p1 = __ldg(&g_cv[e + 1]);
        int2 p2 = __ldg(&g_cv[e + 2]);
        int2 p3 = __ldg(&g_cv[e + 3]);
        if (active) {
            uint2 a = __ldg(&xh[p0.x * ROW4 + lane]);
            uint2 b = __ldg(&xh[p1.x * ROW4 + lane]);
            uint2 c = __ldg(&xh[p2.x * ROW4 + lane]);
            uint2 d = __ldg(&xh[p3.x * ROW4 + lane]);
            fma_h4(acc, a, __int_as_float(p0.y));
            fma_h4(acc, b, __int_as_float(p1.y));
            fma_h4(acc, c, __int_as_float(p2.y));
            fma_h4(acc, d, __int_as_float(p3.y));
        }
    }
    for (; e < end; e++) {
        int2 p0 = __ldg(&g_cv[e]);
        if (active) {
            uint2 a = __ldg(&xh[p0.x * ROW4 + lane]);
            fma_h4(acc, a, __int_as_float(p0.y));
        }
    }
    return acc;
}

// ---------------------------------------------------------------------------
// CSR SpMM layers 1,2: warp per row, fp16 in, fp32 accum, fp16 out
// ---------------------------------------------------------------------------
__global__ void k_spmm_h(const uint2* __restrict__ xh, uint2* __restrict__ dsth) {
    int w = (blockIdx.x * blockDim.x + threadIdx.x) >> 5;
    int lane = threadIdx.x & 31;
    if (w >= N_ITEMS) return;

    int e   = __ldg(&g_ptr[w]);
    int end = __ldg(&g_ptr[w + 1]);     // w+1 <= N_ITEMS < N_TOTAL always valid
    bool active = lane < ROW4;

    float4 acc = csr_row_gather(xh, e, end, lane, active);

    if (active) {
        __half2 lo = __floats2half2_rn(acc.x, acc.y);
        __half2 hi = __floats2half2_rn(acc.z, acc.w);
        uint2 h;
        h.x = *reinterpret_cast<uint32_t*>(&lo);
        h.y = *reinterpret_cast<uint32_t*>(&hi);
        dsth[w * ROW4 + lane] = h;
    }
}

// ---------------------------------------------------------------------------
// Layer 3 (final): acc = A @ x2 ; total = emb + x1 + x2 + acc  (fp32 out)
// ---------------------------------------------------------------------------
__global__ void k_spmm_final(const uint2* __restrict__ x2h,
                             const uint2* __restrict__ x1h,
                             const float4* __restrict__ emb,
                             float4* __restrict__ total) {
    int w = (blockIdx.x * blockDim.x + threadIdx.x) >> 5;
    int lane = threadIdx.x & 31;
    if (w >= N_ITEMS) return;

    int e   = __ldg(&g_ptr[w]);
    int end = __ldg(&g_ptr[w + 1]);
    bool active = lane < ROW4;

    float4 acc = csr_row_gather(x2h, e, end, lane, active);

    if (active) {
        int idx = w * ROW4 + lane;
        float4 t  = __ldg(&emb[idx]);
        float4 x1 = h4_to_f4(__ldg(&x1h[idx]));
        float4 x2 = h4_to_f4(__ldg(&x2h[idx]));
        t.x += x1.x + x2.x + acc.x;
        t.y += x1.y + x2.y + acc.y;
        t.z += x1.z + x2.z + acc.z;
        t.w += x1.w + x2.w + acc.w;
        total[idx] = t;
    }
}

// ---------------------------------------------------------------------------
// user batch: out2[b] = sum over CSR row (N_ITEMS + user[b]) of val * total[col]
// ---------------------------------------------------------------------------
__global__ void k_user_batch(const float4* __restrict__ total,
                             const int* __restrict__ user,
                             float4* __restrict__ out2) {
    int w = (blockIdx.x * blockDim.x + threadIdx.x) >> 5;
    int lane = threadIdx.x & 31;
    if (w >= BATCH) return;

    int u   = N_ITEMS + __ldg(&user[w]);
    int e   = __ldg(&g_ptr[u]);
    int end = (u + 1 < N_TOTAL) ? __ldg(&g_ptr[u + 1]) : NNZ_T;
    bool active = lane < ROW4;

    float4 acc = make_float4(0.f, 0.f, 0.f, 0.f);
    for (; e + 3 < end; e += 4) {
        int2 p0 = __ldg(&g_cv[e]);
        int2 p1 = __ldg(&g_cv[e + 1]);
        int2 p2 = __ldg(&g_cv[e + 2]);
        int2 p3 = __ldg(&g_cv[e + 3]);
        if (active) {
            float4 a = __ldg(&total[p0.x * ROW4 + lane]);
            float4 b = __ldg(&total[p1.x * ROW4 + lane]);
            float4 c = __ldg(&total[p2.x * ROW4 + lane]);
            float4 d = __ldg(&total[p3.x * ROW4 + lane]);
            float v0 = __int_as_float(p0.y), v1 = __int_as_float(p1.y);
            float v2 = __int_as_float(p2.y), v3 = __int_as_float(p3.y);
            acc.x += v0 * a.x + v1 * b.x + v2 * c.x + v3 * d.x;
            acc.y += v0 * a.y + v1 * b.y + v2 * c.y + v3 * d.y;
            acc.z += v0 * a.z + v1 * b.z + v2 * c.z + v3 * d.z;
            acc.w += v0 * a.w + v1 * b.w + v2 * c.w + v3 * d.w;
        }
    }
    for (; e < end; e++) {
        int2 p0 = __ldg(&g_cv[e]);
        if (active) {
            float v0 = __int_as_float(p0.y);
            float4 a = __ldg(&total[p0.x * ROW4 + lane]);
            acc.x += v0 * a.x; acc.y += v0 * a.y;
            acc.z += v0 * a.z; acc.w += v0 * a.w;
        }
    }
    if (active) out2[w * ROW4 + lane] = acc;
}

// ---------------------------------------------------------------------------
// Inputs (metadata order):
//  0 adj_vals f32[3.2M]   1 u_vals f32[1.6M]   2 embedding f32[100000,100]
//  3 user_embedding f32[40000,100]             4 adj_rows i32  5 adj_cols i32
//  6 u_rows i32  7 u_cols i32  8 user i32[4096]
// Output: concat(total [100000*100], user_all[user] [4096*100]) as f32
// ---------------------------------------------------------------------------
extern "C" void kernel_launch(void* const* d_in, const int* in_sizes, int n_in,
                              void* d_out, int out_size) {
    const float* adj_vals = (const float*)d_in[0];
    const float* u_vals   = (const float*)d_in[1];
    const float* emb      = (const float*)d_in[2];
    const int*   adj_rows = (const int*)d_in[4];
    const int*   adj_cols = (const int*)d_in[5];
    const int*   u_rows   = (const int*)d_in[6];
    const int*   u_cols   = (const int*)d_in[7];
    const int*   user     = (const int*)d_in[8];

    float* total = (float*)d_out;                    // [N_ITEMS*EMB]
    float* out2  = total + (size_t)N_ITEMS * EMB;    // [BATCH*EMB]

    uint2 *eh, *h0, *h1;
    int *cnt, *ptr, *run, *bsum;
    cudaGetSymbolAddress((void**)&eh,   g_eh);
    cudaGetSymbolAddress((void**)&h0,   g_h0);
    cudaGetSymbolAddress((void**)&h1,   g_h1);
    cudaGetSymbolAddress((void**)&cnt,  g_cnt);
    cudaGetSymbolAddress((void**)&ptr,  g_ptr);
    cudaGetSymbolAddress((void**)&run,  g_run);
    cudaGetSymbolAddress((void**)&bsum, g_bsum);

    const int TPB = 256;

    // ---- prep: zero combined histogram + fp16 embedding copy ----
    k_prep<<<(N_ITEMS * ROW4 + TPB - 1) / TPB, TPB>>>((const float4*)emb);

    // ---- unified CSR build (items + users in one row space) ----
    k_hist<<<(NNZ_T + TPB - 1) / TPB, TPB>>>(adj_rows, u_rows);
    k_scan1<<<NB_T, SCAN_TPB>>>(cnt, ptr, bsum, N_TOTAL);
    k_scan2<<<1, 1024>>>(bsum, NB_T);
    k_scan3<<<NB_T, SCAN_TPB>>>(ptr, run, bsum, N_TOTAL);
    k_scatter<<<(NNZ_T + TPB - 1) / TPB, TPB>>>(adj_rows, adj_cols, adj_vals,
                                                u_rows, u_cols, u_vals);

    // ---- 3 propagation layers (warp per row, fp16 gathers, fp32 accum) ----
    const int spmm_blocks = (N_ITEMS * 32 + TPB - 1) / TPB;
    k_spmm_h<<<spmm_blocks, TPB>>>(eh, h0);                            // x1
    k_spmm_h<<<spmm_blocks, TPB>>>(h0, h1);                            // x2
    k_spmm_final<<<spmm_blocks, TPB>>>(h1, h0, (const float4*)emb,
                                       (float4*)total);                // total

    // ---- user projection, batch rows only ----
    const int ub_blocks = (BATCH * 32 + TPB - 1) / TPB;
    k_user_batch<<<ub_blocks, TPB>>>((const float4*)total, user, (float4*)out2);
}